// round 16
// baseline (speedup 1.0000x reference)
#include <cuda_runtime.h>
#include <cuda_fp16.h>
#include <cstdint>
#include <math.h>

#define NB 32
#define NS 64
#define NH 512
#define NA 128
#define NWIN 2016
#define NWPAD 2048
#define NLEV 7          // levels 1..6 stored (level 0 unused: width>=2)
#define MT 128
#define KT 32
#define NKT (NH / KT)
#define LDS_A 40        // padded row stride (fp16) -> 80B
#define NSEG 32
#define WSEG (NWPAD / NSEG)   // 64 (padded windows have attn==0)
#define GRIDX (NWPAD / MT)    // 16 score CTAs per batch

// Scratch (static device globals — no allocation).
__device__ __half g_tab16[(NLEV - 1) * NB * NS * NH];  // fp16 max-table, 12.6 MB
__device__ float g_scores[NB * NWPAD];
__device__ float g_attn[NB * NWPAD];             // normalized softmax weights
__device__ int   g_win[NWPAD];                   // packed: s | e2<<8 | k<<16
__device__ int2  g_woff[NWPAD];                  // precomputed element offsets (s,e2)
__device__ __half g_w1t[NA * NH];                // W1^T fp16 (rn), [n][k]
__device__ int   g_cnt[NB];                      // doorbell counters (reset in prep)

// ---------------------------------------------------------------------------
__device__ __forceinline__ uint32_t smem_u32(const void* p) {
    uint32_t a;
    asm("{ .reg .u64 t; cvta.to.shared.u64 t, %1; cvt.u32.u64 %0, t; }" : "=r"(a) : "l"(p));
    return a;
}
#define LDSM_X4(r0, r1, r2, r3, a) \
    asm volatile("ldmatrix.sync.aligned.m8n8.x4.shared.b16 {%0,%1,%2,%3}, [%4];" \
        : "=r"(r0), "=r"(r1), "=r"(r2), "=r"(r3) : "r"(a))
#define CP_ASYNC16(dst, src) \
    asm volatile("cp.async.ca.shared.global [%0], [%1], 16;" :: "r"(dst), "l"(src))
#define CP_COMMIT() asm volatile("cp.async.commit_group;" ::: "memory")
#define CP_WAIT1()  asm volatile("cp.async.wait_group 1;" ::: "memory")
#define CP_WAIT0()  asm volatile("cp.async.wait_group 0;" ::: "memory")

__device__ __forceinline__ void mma_fp16(float* c, const uint32_t* a, const uint32_t* b) {
    asm volatile(
        "mma.sync.aligned.m16n8k16.row.col.f32.f16.f16.f32 "
        "{%0,%1,%2,%3}, {%4,%5,%6,%7}, {%8,%9}, {%0,%1,%2,%3};"
        : "+f"(c[0]), "+f"(c[1]), "+f"(c[2]), "+f"(c[3])
        : "r"(a[0]), "r"(a[1]), "r"(a[2]), "r"(a[3]), "r"(b[0]), "r"(b[1]));
}

__device__ __forceinline__ float4 f4max(float4 a, float4 b) {
    return make_float4(fmaxf(a.x, b.x), fmaxf(a.y, b.y), fmaxf(a.z, b.z), fmaxf(a.w, b.w));
}
__device__ __forceinline__ uint32_t packh2(float a, float b) {
    __half2 h = __floats2half2_rn(a, b);
    return *(uint32_t*)&h;
}
__device__ __forceinline__ uint32_t hmax2u(uint32_t a, uint32_t b) {
    __half2 r = __hmax2(*(__half2*)&a, *(__half2*)&b);
    return *(uint32_t*)&r;
}

// ---------------------------------------------------------------------------
// Prep: grid (8, NB+2), 256 threads.
__global__ void __launch_bounds__(256) k_prep(const float* __restrict__ lstm,
                                              const float* __restrict__ W1,
                                              float* __restrict__ out) {
    int tid = threadIdx.x;
    int by = blockIdx.y, bx = blockIdx.x;

    if (by < NB) {
        int b = by, h0 = bx * 64;
        __shared__ float4 buf[2][NS][16];
        int q = tid & 15, i0 = tid >> 4;
#pragma unroll
        for (int c = 0; c < 4; c++) {
            int i = i0 + c * 16;
            buf[0][i][q] = *(const float4*)(lstm + ((size_t)(b * NS + i)) * NH + h0 + q * 4);
        }
        __syncthreads();
        int cur = 0;
        for (int k = 1; k < NLEV; k++) {
            int half = 1 << (k - 1);
            int nxt = cur ^ 1;
#pragma unroll
            for (int c = 0; c < 4; c++) {
                int i = i0 + c * 16;
                float4 v = buf[cur][i][q];
                if (i + half < NS) v = f4max(v, buf[cur][i + half][q]);
                buf[nxt][i][q] = v;
                uint2 hv;
                hv.x = packh2(v.x, v.y);
                hv.y = packh2(v.z, v.w);
                *(uint2*)(g_tab16 + ((size_t)((k - 1) * NB + b) * NS + i) * NH + h0 + q * 4) = hv;
            }
            __syncthreads();
            cur = nxt;
        }
    } else if (by == NB) {
        int gt = bx * 256 + tid;         // 0..2047
        if (gt < NWPAD) {
            int nn = gt < NWIN ? gt : NWIN - 1;
            int w = 2;
#pragma unroll 1
            for (int ww = 3; ww <= NS; ww++) {
                int F = (129 - ww) * (ww - 2) / 2;
                if (F <= nn) w = ww;
            }
            int Fw = (129 - w) * (w - 2) / 2;
            int s = nn - Fw;
            int k = 31 - __clz(w);
            int e2 = s + w - (1 << k);
            g_win[gt] = s | (e2 << 8) | (k << 16);
            int lvl = (k - 1) * NB * NS * NH;
            g_woff[gt] = make_int2(lvl + s * NH, lvl + e2 * NH);
        }
        if (gt < NB) g_cnt[gt] = 0;      // doorbell reset (graph replay safe)
        for (int i = gt; i < NB * NH; i += 2048) out[i] = 0.f;
    } else {
        // W1^T: block bx covers k in [bx*64, bx*64+64). Coalesced loads.
        int n = tid & 127;
        int kh = tid >> 7;
#pragma unroll 8
        for (int i = 0; i < 32; i++) {
            int k = bx * 64 + kh * 32 + i;
            g_w1t[n * NH + k] = __float2half_rn(W1[k * NA + n]);
        }
    }
}

// ---------------------------------------------------------------------------
// Score kernel: single-pass fp16 HMMA + fused last-CTA softmax per batch.
__global__ void __launch_bounds__(256, 2) k_scores_mma(
    const float* __restrict__ b1, const float* __restrict__ W2)
{
    __shared__ __align__(16) __half aH[2][MT][LDS_A];
    __shared__ __align__(16) __half bH[2][NA][LDS_A];
    __shared__ float sPart[2][MT];
    __shared__ float sb1[NA], sw2[NA];
    __shared__ int s_win[MT];
    __shared__ int s_last;
    __shared__ float red[256];

    int b  = blockIdx.y;
    int n0 = blockIdx.x * MT;
    int tid  = threadIdx.x;
    int wid  = tid >> 5, lane = tid & 31;
    int wm = wid & 3, wn = wid >> 2;

    if (tid < MT) {
        int n = n0 + tid;
        s_win[tid] = g_win[n < NWIN ? n : NWIN - 1];
    }
    if (tid >= MT && tid < MT + NA) { int a = tid - MT; sb1[a] = b1[a]; sw2[a] = W2[a]; }

    float acc[2][8][4];
#pragma unroll
    for (int mt = 0; mt < 2; mt++)
#pragma unroll
        for (int nt = 0; nt < 8; nt++)
#pragma unroll
            for (int j = 0; j < 4; j++) acc[mt][nt][j] = 0.f;

    int am = tid >> 1;
    int ac0 = (tid & 1) * 16;
    int bn = tid >> 1;
    int bco = (tid & 1) * 32;
    const char* w1P = (const char*)g_w1t + (size_t)bn * (NH * 2) + bco;
    uint32_t bD0 = smem_u32(&bH[0][bn][0]) + bco;
    const uint32_t bStride = NA * LDS_A * 2;
    const uint32_t aStride = MT * LDS_A * 2;

    __syncthreads();   // s_win ready

    uint32_t aRow = (uint32_t)(lane & 15);
    uint32_t aCol = (uint32_t)(lane >> 4) * 16u;
    uint32_t bRow = (uint32_t)((lane & 7) + ((lane >> 4) << 3));
    uint32_t bCol = (uint32_t)((lane >> 3) & 1) * 16u;
    uint32_t aBase = smem_u32(&aH[0][0][0]);
    uint32_t bBase = smem_u32(&bH[0][0][0]);

    int wi = s_win[am];
    int ws = wi & 255, we2 = (wi >> 8) & 255, wk = wi >> 16;
    const __half* gbase = g_tab16 + ((size_t)((wk - 1) * NB + b) * NS) * NH + ac0;
    const __half* sRowBase  = gbase + (size_t)ws * NH;
    const __half* e2RowBase = gbase + (size_t)we2 * NH;

    // prologue: B(0) + both rows for t=0
    CP_ASYNC16(bD0,      w1P);
    CP_ASYNC16(bD0 + 16, w1P + 16);
    CP_COMMIT();
    uint4 rsA = *(const uint4*)(sRowBase);
    uint4 rsB = *(const uint4*)(sRowBase + 8);
    uint4 reA = *(const uint4*)(e2RowBase);
    uint4 reB = *(const uint4*)(e2RowBase + 8);

    for (int t = 0; t < NKT; t++) {
        int cur = t & 1, nxt = cur ^ 1;
        bool more = (t + 1 < NKT);

        {
            uint4 r0, r1;
            r0.x = hmax2u(rsA.x, reA.x); r0.y = hmax2u(rsA.y, reA.y);
            r0.z = hmax2u(rsA.z, reA.z); r0.w = hmax2u(rsA.w, reA.w);
            r1.x = hmax2u(rsB.x, reB.x); r1.y = hmax2u(rsB.y, reB.y);
            r1.z = hmax2u(rsB.z, reB.z); r1.w = hmax2u(rsB.w, reB.w);
            *(uint4*)&aH[cur][am][ac0]     = r0;
            *(uint4*)&aH[cur][am][ac0 + 8] = r1;
        }
        if (more) {
            const char* hp = w1P + (t + 1) * (KT * 2);
            uint32_t hd = bD0 + (uint32_t)nxt * bStride;
            CP_ASYNC16(hd,      hp);
            CP_ASYNC16(hd + 16, hp + 16);
            CP_COMMIT();
            CP_WAIT1();
        } else {
            CP_WAIT0();
        }
        __syncthreads();

        if (more) {
            const __half* ps = sRowBase  + (t + 1) * KT;
            const __half* pe = e2RowBase + (t + 1) * KT;
            rsA = *(const uint4*)(ps);
            rsB = *(const uint4*)(ps + 8);
            reA = *(const uint4*)(pe);
            reB = *(const uint4*)(pe + 8);
        }

        uint32_t aB = aBase + (uint32_t)cur * aStride;
        uint32_t bB = bBase + (uint32_t)cur * bStride;
#pragma unroll
        for (int ks = 0; ks < 2; ks++) {
            uint32_t kOff = (uint32_t)ks * 32u;
            uint32_t A[2][4];
#pragma unroll
            for (int mt = 0; mt < 2; mt++) {
                uint32_t row = (uint32_t)(wm * 32 + mt * 16) + aRow;
                uint32_t off = row * (LDS_A * 2) + kOff + aCol;
                LDSM_X4(A[mt][0], A[mt][1], A[mt][2], A[mt][3], aB + off);
            }
#pragma unroll
            for (int np = 0; np < 4; np++) {
                uint32_t nrow = (uint32_t)(wn * 64 + np * 16) + bRow;
                uint32_t off = nrow * (LDS_A * 2) + kOff + bCol;
                uint32_t B[4];
                LDSM_X4(B[0], B[1], B[2], B[3], bB + off);
#pragma unroll
                for (int mt = 0; mt < 2; mt++) {
#pragma unroll
                    for (int h = 0; h < 2; h++) {
                        mma_fp16(acc[mt][np * 2 + h], A[mt], &B[h * 2]);
                    }
                }
            }
        }
    }
    __syncthreads();

    // epilogue: relu(acc + b1) dot W2, reduce over n
    int gq = lane >> 2;
    int gr = lane & 3;
#pragma unroll
    for (int mt = 0; mt < 2; mt++) {
        float p0 = 0.f, p1 = 0.f;
#pragma unroll
        for (int nt = 0; nt < 8; nt++) {
            int col = wn * 64 + nt * 8 + gr * 2;
            float b1a = sb1[col], b1b = sb1[col + 1];
            float w2a = sw2[col], w2b = sw2[col + 1];
            p0 = fmaf(fmaxf(acc[mt][nt][0] + b1a, 0.f), w2a, p0);
            p0 = fmaf(fmaxf(acc[mt][nt][1] + b1b, 0.f), w2b, p0);
            p1 = fmaf(fmaxf(acc[mt][nt][2] + b1a, 0.f), w2a, p1);
            p1 = fmaf(fmaxf(acc[mt][nt][3] + b1b, 0.f), w2b, p1);
        }
#pragma unroll
        for (int off = 1; off <= 2; off <<= 1) {
            p0 += __shfl_xor_sync(0xffffffffu, p0, off);
            p1 += __shfl_xor_sync(0xffffffffu, p1, off);
        }
        if (gr == 0) {
            int row = wm * 32 + mt * 16 + gq;
            sPart[wn][row]     = p0;
            sPart[wn][row + 8] = p1;
        }
    }
    __syncthreads();
    if (tid < MT) {
        int n = n0 + tid;
        if (n < NWIN)
            g_scores[b * NWPAD + n] = sPart[0][tid] + sPart[1][tid];
    }

    // ---- fused softmax: last CTA per batch computes attn for the whole batch
    __threadfence();
    __syncthreads();
    if (tid == 0) {
        int c = atomicAdd(&g_cnt[b], 1);
        s_last = (c == GRIDX - 1) ? 1 : 0;
    }
    __syncthreads();
    if (s_last) {
        __threadfence();   // acquire: other CTAs' score writes now visible
        float mx = -1e30f;
        for (int n = tid; n < NWIN; n += 256)
            mx = fmaxf(mx, g_scores[b * NWPAD + n]);
        red[tid] = mx;
        __syncthreads();
        for (int s = 128; s > 0; s >>= 1) {
            if (tid < s) red[tid] = fmaxf(red[tid], red[tid + s]);
            __syncthreads();
        }
        mx = red[0];
        __syncthreads();
        float sum = 0.f;
        float e[8];
#pragma unroll
        for (int c = 0; c < 8; c++) {
            int n = c * 256 + tid;
            e[c] = (n < NWIN) ? __expf(g_scores[b * NWPAD + n] - mx) : 0.f;
            sum += e[c];
        }
        red[tid] = sum;
        __syncthreads();
        for (int s = 128; s > 0; s >>= 1) {
            if (tid < s) red[tid] += red[tid + s];
            __syncthreads();
        }
        float inv = 1.f / red[0];
#pragma unroll
        for (int c = 0; c < 8; c++) {
            int n = c * 256 + tid;
            g_attn[b * NWPAD + n] = e[c] * inv;
        }
    }
}

// ---------------------------------------------------------------------------
// Partial weighted sum: grid (NB, NSEG=32), 256 thr, 2 h per thread,
// j unrolled x4 -> MLP 8. Segments span NWPAD; padded windows have attn=0.
__global__ void __launch_bounds__(256) k_out_part(float* __restrict__ out) {
    int b = blockIdx.x;
    int seg = blockIdx.y;
    int tid = threadIdx.x;
    int h0 = tid * 2;
    __shared__ float sattn[WSEG];
    __shared__ int2  soff[WSEG];

    int j0 = seg * WSEG;
    if (tid < WSEG) {
        sattn[tid] = g_attn[b * NWPAD + j0 + tid];
        soff[tid]  = g_woff[j0 + tid];
    }
    __syncthreads();

    const __half* base = g_tab16 + (size_t)b * NS * NH + h0;
    float a0 = 0.f, a1 = 0.f, b0 = 0.f, b1v = 0.f;
    float c0 = 0.f, c1 = 0.f, d0 = 0.f, d1 = 0.f;
#pragma unroll 2
    for (int j = 0; j < WSEG; j += 4) {
        float at0 = sattn[j], at1 = sattn[j + 1];
        float at2 = sattn[j + 2], at3 = sattn[j + 3];
        int2 o0 = soff[j], o1 = soff[j + 1], o2 = soff[j + 2], o3 = soff[j + 3];
        uint32_t x0 = *(const uint32_t*)(base + o0.x);
        uint32_t y0 = *(const uint32_t*)(base + o0.y);
        uint32_t x1 = *(const uint32_t*)(base + o1.x);
        uint32_t y1 = *(const uint32_t*)(base + o1.y);
        uint32_t x2 = *(const uint32_t*)(base + o2.x);
        uint32_t y2 = *(const uint32_t*)(base + o2.y);
        uint32_t x3 = *(const uint32_t*)(base + o3.x);
        uint32_t y3 = *(const uint32_t*)(base + o3.y);
        uint32_t m0 = hmax2u(x0, y0);
        uint32_t m1 = hmax2u(x1, y1);
        uint32_t m2 = hmax2u(x2, y2);
        uint32_t m3 = hmax2u(x3, y3);
        float2 f0 = __half22float2(*(__half2*)&m0);
        float2 f1 = __half22float2(*(__half2*)&m1);
        float2 f2 = __half22float2(*(__half2*)&m2);
        float2 f3 = __half22float2(*(__half2*)&m3);
        a0 = fmaf(at0, f0.x, a0);
        a1 = fmaf(at0, f0.y, a1);
        b0 = fmaf(at1, f1.x, b0);
        b1v = fmaf(at1, f1.y, b1v);
        c0 = fmaf(at2, f2.x, c0);
        c1 = fmaf(at2, f2.y, c1);
        d0 = fmaf(at3, f3.x, d0);
        d1 = fmaf(at3, f3.y, d1);
    }
    float* op = out + b * NH + h0;
    atomicAdd(op,     (a0 + b0) + (c0 + d0));
    atomicAdd(op + 1, (a1 + b1v) + (c1 + d1));
}

// ---------------------------------------------------------------------------
extern "C" void kernel_launch(void* const* d_in, const int* in_sizes, int n_in,
                              void* d_out, int out_size) {
    const float* lstm = (const float*)d_in[0];
    const float* W1   = (const float*)d_in[1];
    const float* b1   = (const float*)d_in[2];
    const float* W2   = (const float*)d_in[3];
    float* out = (float*)d_out;

    k_prep<<<dim3(8, NB + 2), 256>>>(lstm, W1, out);
    k_scores_mma<<<dim3(GRIDX, NB), 256>>>(b1, W2);
    k_out_part<<<dim3(NB, NSEG), 256>>>(out);
}

// round 17
// speedup vs baseline: 1.0904x; 1.0904x over previous
#include <cuda_runtime.h>
#include <cuda_fp16.h>
#include <cstdint>
#include <math.h>

#define NB 32
#define NS 64
#define NH 512
#define NA 128
#define NWIN 2016
#define NWPAD 2048
#define NLEV 7          // levels 1..6 stored (level 0 unused: width>=2)
#define MT 128
#define KT 32
#define NKT (NH / KT)
#define LDS_A 40        // padded row stride (fp16) -> 80B
#define NSEG 32
#define WSEG (NWPAD / NSEG)   // 64 (padded windows have attn==0)

// Scratch (static device globals — no allocation).
__device__ __half g_tab16[(NLEV - 1) * NB * NS * NH];  // fp16 max-table, 12.6 MB
__device__ float g_scores[NB * NWPAD];
__device__ float g_attn[NB * NWPAD];             // normalized softmax weights
__device__ int   g_win[NWPAD];                   // packed: s | e2<<8 | k<<16
__device__ int2  g_woff[NWPAD];                  // precomputed element offsets (s,e2)
__device__ __half g_w1t[NA * NH];                // W1^T fp16 (rn), [n][k]

// ---------------------------------------------------------------------------
__device__ __forceinline__ uint32_t smem_u32(const void* p) {
    uint32_t a;
    asm("{ .reg .u64 t; cvta.to.shared.u64 t, %1; cvt.u32.u64 %0, t; }" : "=r"(a) : "l"(p));
    return a;
}
#define LDSM_X4(r0, r1, r2, r3, a) \
    asm volatile("ldmatrix.sync.aligned.m8n8.x4.shared.b16 {%0,%1,%2,%3}, [%4];" \
        : "=r"(r0), "=r"(r1), "=r"(r2), "=r"(r3) : "r"(a))
#define CP_ASYNC16(dst, src) \
    asm volatile("cp.async.ca.shared.global [%0], [%1], 16;" :: "r"(dst), "l"(src))
#define CP_COMMIT() asm volatile("cp.async.commit_group;" ::: "memory")
#define CP_WAIT1()  asm volatile("cp.async.wait_group 1;" ::: "memory")
#define CP_WAIT0()  asm volatile("cp.async.wait_group 0;" ::: "memory")

__device__ __forceinline__ void mma_fp16(float* c, const uint32_t* a, const uint32_t* b) {
    asm volatile(
        "mma.sync.aligned.m16n8k16.row.col.f32.f16.f16.f32 "
        "{%0,%1,%2,%3}, {%4,%5,%6,%7}, {%8,%9}, {%0,%1,%2,%3};"
        : "+f"(c[0]), "+f"(c[1]), "+f"(c[2]), "+f"(c[3])
        : "r"(a[0]), "r"(a[1]), "r"(a[2]), "r"(a[3]), "r"(b[0]), "r"(b[1]));
}

__device__ __forceinline__ float4 f4max(float4 a, float4 b) {
    return make_float4(fmaxf(a.x, b.x), fmaxf(a.y, b.y), fmaxf(a.z, b.z), fmaxf(a.w, b.w));
}
__device__ __forceinline__ uint32_t packh2(float a, float b) {
    __half2 h = __floats2half2_rn(a, b);
    return *(uint32_t*)&h;
}
__device__ __forceinline__ uint32_t hmax2u(uint32_t a, uint32_t b) {
    __half2 r = __hmax2(*(__half2*)&a, *(__half2*)&b);
    return *(uint32_t*)&r;
}

// ---------------------------------------------------------------------------
// Prep: grid (16, NB+2), 256 threads. Table branch: 32-wide h chunks (2x CTAs).
__global__ void __launch_bounds__(256) k_prep(const float* __restrict__ lstm,
                                              const float* __restrict__ W1,
                                              float* __restrict__ out) {
    int tid = threadIdx.x;
    int by = blockIdx.y, bx = blockIdx.x;

    if (by < NB) {
        int b = by, h0 = bx * 32;
        __shared__ float4 buf[2][NS][8];          // 64 i x 32 h (8 float4)
        int q = tid & 7, i0 = tid >> 3;           // warp: 4 rows x 8 quads
#pragma unroll
        for (int c = 0; c < 2; c++) {
            int i = i0 + c * 32;
            buf[0][i][q] = *(const float4*)(lstm + ((size_t)(b * NS + i)) * NH + h0 + q * 4);
        }
        __syncthreads();
        int cur = 0;
        for (int k = 1; k < NLEV; k++) {
            int half = 1 << (k - 1);
            int nxt = cur ^ 1;
#pragma unroll
            for (int c = 0; c < 2; c++) {
                int i = i0 + c * 32;
                float4 v = buf[cur][i][q];
                if (i + half < NS) v = f4max(v, buf[cur][i + half][q]);
                buf[nxt][i][q] = v;
                uint2 hv;
                hv.x = packh2(v.x, v.y);
                hv.y = packh2(v.z, v.w);
                *(uint2*)(g_tab16 + ((size_t)((k - 1) * NB + b) * NS + i) * NH + h0 + q * 4) = hv;
            }
            __syncthreads();
            cur = nxt;
        }
    } else if (by == NB) {
        int gt = bx * 256 + tid;         // 0..4095
        if (gt < NWPAD) {
            int nn = gt < NWIN ? gt : NWIN - 1;
            int w = 2;
#pragma unroll 1
            for (int ww = 3; ww <= NS; ww++) {
                int F = (129 - ww) * (ww - 2) / 2;
                if (F <= nn) w = ww;
            }
            int Fw = (129 - w) * (w - 2) / 2;
            int s = nn - Fw;
            int k = 31 - __clz(w);
            int e2 = s + w - (1 << k);
            g_win[gt] = s | (e2 << 8) | (k << 16);
            int lvl = (k - 1) * NB * NS * NH;
            g_woff[gt] = make_int2(lvl + s * NH, lvl + e2 * NH);
        }
        for (int i = gt; i < NB * NH; i += 4096) out[i] = 0.f;
    } else {
        // W1^T: block bx covers k in [bx*32, bx*32+32). Coalesced loads.
        int n = tid & 127;
        int kh = tid >> 7;               // 0..1
#pragma unroll 8
        for (int i = 0; i < 16; i++) {
            int k = bx * 32 + kh * 16 + i;
            g_w1t[n * NH + k] = __float2half_rn(W1[k * NA + n]);
        }
    }
}

// ---------------------------------------------------------------------------
// Score kernel: single-pass fp16 HMMA. Both gather rows register-prefetched,
// double-buffered A and B smem stages, ONE __syncthreads per k-tile.
__global__ void __launch_bounds__(256, 2) k_scores_mma(
    const float* __restrict__ b1, const float* __restrict__ W2)
{
    __shared__ __align__(16) __half aH[2][MT][LDS_A];
    __shared__ __align__(16) __half bH[2][NA][LDS_A];
    __shared__ float sPart[2][MT];
    __shared__ float sb1[NA], sw2[NA];
    __shared__ int s_win[MT];

    int b  = blockIdx.y;
    int n0 = blockIdx.x * MT;
    int tid  = threadIdx.x;
    int wid  = tid >> 5, lane = tid & 31;
    int wm = wid & 3, wn = wid >> 2;

    if (tid < MT) {
        int n = n0 + tid;
        s_win[tid] = g_win[n < NWIN ? n : NWIN - 1];
    }
    if (tid >= MT && tid < MT + NA) { int a = tid - MT; sb1[a] = b1[a]; sw2[a] = W2[a]; }

    float acc[2][8][4];
#pragma unroll
    for (int mt = 0; mt < 2; mt++)
#pragma unroll
        for (int nt = 0; nt < 8; nt++)
#pragma unroll
            for (int j = 0; j < 4; j++) acc[mt][nt][j] = 0.f;

    int am = tid >> 1;
    int ac0 = (tid & 1) * 16;
    int bn = tid >> 1;
    int bco = (tid & 1) * 32;
    const char* w1P = (const char*)g_w1t + (size_t)bn * (NH * 2) + bco;
    uint32_t bD0 = smem_u32(&bH[0][bn][0]) + bco;
    const uint32_t bStride = NA * LDS_A * 2;
    const uint32_t aStride = MT * LDS_A * 2;

    __syncthreads();   // s_win ready

    uint32_t aRow = (uint32_t)(lane & 15);
    uint32_t aCol = (uint32_t)(lane >> 4) * 16u;
    uint32_t bRow = (uint32_t)((lane & 7) + ((lane >> 4) << 3));
    uint32_t bCol = (uint32_t)((lane >> 3) & 1) * 16u;
    uint32_t aBase = smem_u32(&aH[0][0][0]);
    uint32_t bBase = smem_u32(&bH[0][0][0]);

    int wi = s_win[am];
    int ws = wi & 255, we2 = (wi >> 8) & 255, wk = wi >> 16;
    const __half* gbase = g_tab16 + ((size_t)((wk - 1) * NB + b) * NS) * NH + ac0;
    const __half* sRowBase  = gbase + (size_t)ws * NH;
    const __half* e2RowBase = gbase + (size_t)we2 * NH;

    // prologue: B(0) + both rows for t=0
    CP_ASYNC16(bD0,      w1P);
    CP_ASYNC16(bD0 + 16, w1P + 16);
    CP_COMMIT();
    uint4 rsA = *(const uint4*)(sRowBase);
    uint4 rsB = *(const uint4*)(sRowBase + 8);
    uint4 reA = *(const uint4*)(e2RowBase);
    uint4 reB = *(const uint4*)(e2RowBase + 8);

    for (int t = 0; t < NKT; t++) {
        int cur = t & 1, nxt = cur ^ 1;
        bool more = (t + 1 < NKT);

        {
            uint4 r0, r1;
            r0.x = hmax2u(rsA.x, reA.x); r0.y = hmax2u(rsA.y, reA.y);
            r0.z = hmax2u(rsA.z, reA.z); r0.w = hmax2u(rsA.w, reA.w);
            r1.x = hmax2u(rsB.x, reB.x); r1.y = hmax2u(rsB.y, reB.y);
            r1.z = hmax2u(rsB.z, reB.z); r1.w = hmax2u(rsB.w, reB.w);
            *(uint4*)&aH[cur][am][ac0]     = r0;
            *(uint4*)&aH[cur][am][ac0 + 8] = r1;
        }
        if (more) {
            const char* hp = w1P + (t + 1) * (KT * 2);
            uint32_t hd = bD0 + (uint32_t)nxt * bStride;
            CP_ASYNC16(hd,      hp);
            CP_ASYNC16(hd + 16, hp + 16);
            CP_COMMIT();
            CP_WAIT1();
        } else {
            CP_WAIT0();
        }
        __syncthreads();

        if (more) {
            const __half* ps = sRowBase  + (t + 1) * KT;
            const __half* pe = e2RowBase + (t + 1) * KT;
            rsA = *(const uint4*)(ps);
            rsB = *(const uint4*)(ps + 8);
            reA = *(const uint4*)(pe);
            reB = *(const uint4*)(pe + 8);
        }

        uint32_t aB = aBase + (uint32_t)cur * aStride;
        uint32_t bB = bBase + (uint32_t)cur * bStride;
#pragma unroll
        for (int ks = 0; ks < 2; ks++) {
            uint32_t kOff = (uint32_t)ks * 32u;
            uint32_t A[2][4];
#pragma unroll
            for (int mt = 0; mt < 2; mt++) {
                uint32_t row = (uint32_t)(wm * 32 + mt * 16) + aRow;
                uint32_t off = row * (LDS_A * 2) + kOff + aCol;
                LDSM_X4(A[mt][0], A[mt][1], A[mt][2], A[mt][3], aB + off);
            }
#pragma unroll
            for (int np = 0; np < 4; np++) {
                uint32_t nrow = (uint32_t)(wn * 64 + np * 16) + bRow;
                uint32_t off = nrow * (LDS_A * 2) + kOff + bCol;
                uint32_t B[4];
                LDSM_X4(B[0], B[1], B[2], B[3], bB + off);
#pragma unroll
                for (int mt = 0; mt < 2; mt++) {
#pragma unroll
                    for (int h = 0; h < 2; h++) {
                        mma_fp16(acc[mt][np * 2 + h], A[mt], &B[h * 2]);
                    }
                }
            }
        }
    }
    __syncthreads();

    // epilogue: relu(acc + b1) dot W2, reduce over n
    int gq = lane >> 2;
    int gr = lane & 3;
#pragma unroll
    for (int mt = 0; mt < 2; mt++) {
        float p0 = 0.f, p1 = 0.f;
#pragma unroll
        for (int nt = 0; nt < 8; nt++) {
            int col = wn * 64 + nt * 8 + gr * 2;
            float b1a = sb1[col], b1b = sb1[col + 1];
            float w2a = sw2[col], w2b = sw2[col + 1];
            p0 = fmaf(fmaxf(acc[mt][nt][0] + b1a, 0.f), w2a, p0);
            p0 = fmaf(fmaxf(acc[mt][nt][1] + b1b, 0.f), w2b, p0);
            p1 = fmaf(fmaxf(acc[mt][nt][2] + b1a, 0.f), w2a, p1);
            p1 = fmaf(fmaxf(acc[mt][nt][3] + b1b, 0.f), w2b, p1);
        }
#pragma unroll
        for (int off = 1; off <= 2; off <<= 1) {
            p0 += __shfl_xor_sync(0xffffffffu, p0, off);
            p1 += __shfl_xor_sync(0xffffffffu, p1, off);
        }
        if (gr == 0) {
            int row = wm * 32 + mt * 16 + gq;
            sPart[wn][row]     = p0;
            sPart[wn][row + 8] = p1;
        }
    }
    __syncthreads();
    if (tid < MT) {
        int n = n0 + tid;
        if (n < NWIN)
            g_scores[b * NWPAD + n] = sPart[0][tid] + sPart[1][tid];
    }
}

// ---------------------------------------------------------------------------
// Softmax: 32 CTAs, 256 thr. Writes NORMALIZED attn (0 for padded windows).
__global__ void __launch_bounds__(256) k_attn() {
    int b = blockIdx.x;
    int tid = threadIdx.x;
    __shared__ float red[256];

    float mx = -1e30f;
    for (int n = tid; n < NWIN; n += 256)
        mx = fmaxf(mx, g_scores[b * NWPAD + n]);
    red[tid] = mx;
    __syncthreads();
    for (int s = 128; s > 0; s >>= 1) {
        if (tid < s) red[tid] = fmaxf(red[tid], red[tid + s]);
        __syncthreads();
    }
    mx = red[0];
    __syncthreads();
    float sum = 0.f;
    float e[8];
#pragma unroll
    for (int c = 0; c < 8; c++) {
        int n = c * 256 + tid;
        e[c] = (n < NWIN) ? __expf(g_scores[b * NWPAD + n] - mx) : 0.f;
        sum += e[c];
    }
    red[tid] = sum;
    __syncthreads();
    for (int s = 128; s > 0; s >>= 1) {
        if (tid < s) red[tid] += red[tid + s];
        __syncthreads();
    }
    float inv = 1.f / red[0];
#pragma unroll
    for (int c = 0; c < 8; c++) {
        int n = c * 256 + tid;
        if (n < NWPAD) g_attn[b * NWPAD + n] = e[c] * inv;
    }
}

// ---------------------------------------------------------------------------
// Partial weighted sum: grid (NB, NSEG=32), 256 thr, 2 h per thread,
// j unrolled x4 -> MLP 8. Segments span NWPAD; padded windows have attn=0.
__global__ void __launch_bounds__(256) k_out_part(float* __restrict__ out) {
    int b = blockIdx.x;
    int seg = blockIdx.y;
    int tid = threadIdx.x;
    int h0 = tid * 2;
    __shared__ float sattn[WSEG];
    __shared__ int2  soff[WSEG];

    int j0 = seg * WSEG;
    if (tid < WSEG) {
        sattn[tid] = g_attn[b * NWPAD + j0 + tid];
        soff[tid]  = g_woff[j0 + tid];
    }
    __syncthreads();

    const __half* base = g_tab16 + (size_t)b * NS * NH + h0;
    float a0 = 0.f, a1 = 0.f, b0 = 0.f, b1v = 0.f;
    float c0 = 0.f, c1 = 0.f, d0 = 0.f, d1 = 0.f;
#pragma unroll 2
    for (int j = 0; j < WSEG; j += 4) {
        float at0 = sattn[j], at1 = sattn[j + 1];
        float at2 = sattn[j + 2], at3 = sattn[j + 3];
        int2 o0 = soff[j], o1 = soff[j + 1], o2 = soff[j + 2], o3 = soff[j + 3];
        uint32_t x0 = *(const uint32_t*)(base + o0.x);
        uint32_t y0 = *(const uint32_t*)(base + o0.y);
        uint32_t x1 = *(const uint32_t*)(base + o1.x);
        uint32_t y1 = *(const uint32_t*)(base + o1.y);
        uint32_t x2 = *(const uint32_t*)(base + o2.x);
        uint32_t y2 = *(const uint32_t*)(base + o2.y);
        uint32_t x3 = *(const uint32_t*)(base + o3.x);
        uint32_t y3 = *(const uint32_t*)(base + o3.y);
        uint32_t m0 = hmax2u(x0, y0);
        uint32_t m1 = hmax2u(x1, y1);
        uint32_t m2 = hmax2u(x2, y2);
        uint32_t m3 = hmax2u(x3, y3);
        float2 f0 = __half22float2(*(__half2*)&m0);
        float2 f1 = __half22float2(*(__half2*)&m1);
        float2 f2 = __half22float2(*(__half2*)&m2);
        float2 f3 = __half22float2(*(__half2*)&m3);
        a0 = fmaf(at0, f0.x, a0);
        a1 = fmaf(at0, f0.y, a1);
        b0 = fmaf(at1, f1.x, b0);
        b1v = fmaf(at1, f1.y, b1v);
        c0 = fmaf(at2, f2.x, c0);
        c1 = fmaf(at2, f2.y, c1);
        d0 = fmaf(at3, f3.x, d0);
        d1 = fmaf(at3, f3.y, d1);
    }
    float* op = out + b * NH + h0;
    atomicAdd(op,     (a0 + b0) + (c0 + d0));
    atomicAdd(op + 1, (a1 + b1v) + (c1 + d1));
}

// ---------------------------------------------------------------------------
extern "C" void kernel_launch(void* const* d_in, const int* in_sizes, int n_in,
                              void* d_out, int out_size) {
    const float* lstm = (const float*)d_in[0];
    const float* W1   = (const float*)d_in[1];
    const float* b1   = (const float*)d_in[2];
    const float* W2   = (const float*)d_in[3];
    float* out = (float*)d_out;

    k_prep<<<dim3(16, NB + 2), 256>>>(lstm, W1, out);
    k_scores_mma<<<dim3(NWPAD / MT, NB), 256>>>(b1, W2);
    k_attn<<<NB, 256>>>();
    k_out_part<<<dim3(NB, NSEG), 256>>>(out);
}